// round 3
// baseline (speedup 1.0000x reference)
#include <cuda_runtime.h>
#include <math.h>
#include <stdint.h>

// Problem constants (fixed shapes from setup_inputs)
#define BSZ   4096      // B*S
#define HID   2048      // H
#define KD    256       // KDIM
#define KNUM  1024      // key_num
#define NCOL  4096      // head * key_num * rank = 2*1024*2
#define VNUM  262144    // value_num = 2^18
#define VDIM  256
#define NEG_INF (-3.402823466e38f)

// ---------------- scratch (device globals; no allocation allowed) -----------
__device__ float g_qraw[(size_t)BSZ * 512];
__device__ float g_q1[(size_t)BSZ * KD];
__device__ float g_q2[(size_t)BSZ * KD];
__device__ float g_Bk1[(size_t)NCOL * KD];
__device__ float g_Bk2[(size_t)NCOL * KD];
__device__ float g_C1[(size_t)BSZ * NCOL];
__device__ float g_C2[(size_t)BSZ * NCOL];
__device__ float g_agg[(size_t)BSZ * 1024];

// ---------------- packed f32x2 FMA (Blackwell) ------------------------------
__device__ __forceinline__ unsigned long long ffma2(
    unsigned long long a, unsigned long long b, unsigned long long c)
{
    unsigned long long d;
    asm("fma.rn.f32x2 %0, %1, %2, %3;" : "=l"(d) : "l"(a), "l"(b), "l"(c));
    return d;
}
__device__ __forceinline__ unsigned long long bcast2(float x)
{
    unsigned long long p;
    asm("mov.b64 %0, {%1, %1};" : "=l"(p) : "r"(__float_as_uint(x)));
    return p;
}

// ---------------- fp32 SGEMM: C[M,N] = A[M,K] * B ---------------------------
// BT=false: B is (K,N) row-major (NN).  BT=true: B is (N,K) row-major (NT).
// 128x128 tile, 256 threads, 8x8 microtile, double-buffered smem, f32x2 FMA.
// Requires M%128==0, N%128==0, K%16==0 (true at all call sites).

template <bool BT>
__device__ __forceinline__ void gload(
    const float* __restrict__ A, const float* __restrict__ B,
    int N, int K, int m0, int n0, int k0, int tid,
    float4 pa[2], float4 pb[2])
{
#pragma unroll
    for (int i = 0; i < 2; i++) {
        int idx4 = tid + i * 256;
        int row = idx4 >> 2, seg = idx4 & 3;
        pa[i] = *(const float4*)&A[(size_t)(m0 + row) * K + k0 + seg * 4];
    }
    if (!BT) {
#pragma unroll
        for (int i = 0; i < 2; i++) {
            int idx4 = tid + i * 256;
            int kk = idx4 >> 5, seg = idx4 & 31;
            pb[i] = *(const float4*)&B[(size_t)(k0 + kk) * N + n0 + seg * 4];
        }
    } else {
#pragma unroll
        for (int i = 0; i < 2; i++) {
            int idx4 = tid + i * 256;
            int nrow = idx4 >> 2, seg = idx4 & 3;
            pb[i] = *(const float4*)&B[(size_t)(n0 + nrow) * K + k0 + seg * 4];
        }
    }
}

template <bool BT>
__device__ __forceinline__ void sstore(
    float (*As)[132], float (*Bs)[132], int tid,
    const float4 pa[2], const float4 pb[2])
{
#pragma unroll
    for (int i = 0; i < 2; i++) {
        int idx4 = tid + i * 256;
        int row = idx4 >> 2, seg = idx4 & 3;
        As[seg * 4 + 0][row] = pa[i].x;
        As[seg * 4 + 1][row] = pa[i].y;
        As[seg * 4 + 2][row] = pa[i].z;
        As[seg * 4 + 3][row] = pa[i].w;
    }
    if (!BT) {
#pragma unroll
        for (int i = 0; i < 2; i++) {
            int idx4 = tid + i * 256;
            int kk = idx4 >> 5, seg = idx4 & 31;
            *(float4*)&Bs[kk][seg * 4] = pb[i];
        }
    } else {
#pragma unroll
        for (int i = 0; i < 2; i++) {
            int idx4 = tid + i * 256;
            int nrow = idx4 >> 2, seg = idx4 & 3;
            Bs[seg * 4 + 0][nrow] = pb[i].x;
            Bs[seg * 4 + 1][nrow] = pb[i].y;
            Bs[seg * 4 + 2][nrow] = pb[i].z;
            Bs[seg * 4 + 3][nrow] = pb[i].w;
        }
    }
}

template <bool BT>
__global__ __launch_bounds__(256, 2) void sgemm_kernel(
    const float* __restrict__ A, const float* __restrict__ B,
    float* __restrict__ C, int M, int N, int K)
{
    __shared__ float As[2][16][132];   // [buf][k][m]; 132 keeps 16B row alignment
    __shared__ float Bs[2][16][132];   // [buf][k][n]

    const int tid = threadIdx.x;
    const int tx = tid & 15;           // 0..15 -> 8 cols each
    const int ty = tid >> 4;           // 0..15 -> 8 rows each
    const int m0 = blockIdx.y * 128;
    const int n0 = blockIdx.x * 128;

    unsigned long long acc[8][4];      // 8 rows x 4 packed column-pairs
#pragma unroll
    for (int i = 0; i < 8; i++)
#pragma unroll
        for (int j = 0; j < 4; j++) acc[i][j] = 0ull;

    // prologue: tile 0 -> buffer 0
    {
        float4 pa[2], pb[2];
        gload<BT>(A, B, N, K, m0, n0, 0, tid, pa, pb);
        sstore<BT>(As[0], Bs[0], tid, pa, pb);
    }
    __syncthreads();

    const int nk = K >> 4;
    int bf = 0;
    for (int t = 0; t < nk; t++) {
        float4 pa[2], pb[2];
        const bool more = (t + 1 < nk);
        if (more)
            gload<BT>(A, B, N, K, m0, n0, (t + 1) << 4, tid, pa, pb);

#pragma unroll
        for (int kk = 0; kk < 16; kk++) {
            float4 a0 = *(const float4*)&As[bf][kk][ty * 8 + 0];
            float4 a1 = *(const float4*)&As[bf][kk][ty * 8 + 4];
            ulonglong2 bq0 = *(const ulonglong2*)&Bs[bf][kk][tx * 8 + 0];
            ulonglong2 bq1 = *(const ulonglong2*)&Bs[bf][kk][tx * 8 + 4];
            unsigned long long bp[4] = {bq0.x, bq0.y, bq1.x, bq1.y};
            float ra[8] = {a0.x, a0.y, a0.z, a0.w, a1.x, a1.y, a1.z, a1.w};
#pragma unroll
            for (int i = 0; i < 8; i++) {
                unsigned long long ap = bcast2(ra[i]);
#pragma unroll
                for (int j = 0; j < 4; j++)
                    acc[i][j] = ffma2(ap, bp[j], acc[i][j]);
            }
        }

        if (more)
            sstore<BT>(As[bf ^ 1], Bs[bf ^ 1], tid, pa, pb);
        __syncthreads();
        bf ^= 1;
    }

#pragma unroll
    for (int i = 0; i < 8; i++) {
        float2 p0 = *reinterpret_cast<float2*>(&acc[i][0]);
        float2 p1 = *reinterpret_cast<float2*>(&acc[i][1]);
        float2 p2 = *reinterpret_cast<float2*>(&acc[i][2]);
        float2 p3 = *reinterpret_cast<float2*>(&acc[i][3]);
        size_t row = (size_t)(m0 + ty * 8 + i) * N + n0 + tx * 8;
        *(float4*)&C[row]     = make_float4(p0.x, p0.y, p1.x, p1.y);
        *(float4*)&C[row + 4] = make_float4(p2.x, p2.y, p3.x, p3.y);
    }
}

// ---------------- keys normalization -> transposed layout -------------------
// keys: (head=2, 2, KNUM, KD, rank=2). Normalize over d (KD) per (h,s,k,r),
// scale by knorm_w[d], write Bk[s][((h*KNUM+k)*2 + r)*KD + d].
__global__ __launch_bounds__(256) void keysn_kernel(
    const float* __restrict__ keys, const float* __restrict__ knw,
    float* __restrict__ Bk1, float* __restrict__ Bk2)
{
    __shared__ float2 red[256];
    int blk = blockIdx.x;                 // 0..4095
    int k = blk & (KNUM - 1);
    int s = (blk >> 10) & 1;
    int h = blk >> 11;
    int tid = threadIdx.x;                // d index

    const float* base = keys + ((((size_t)h * 2 + s) * KNUM + k) * KD) * 2;
    float2 x = *(const float2*)&base[tid * 2];   // (d=tid, r=0), (r=1)

    red[tid] = x;
    __syncthreads();
    for (int st = 128; st > 0; st >>= 1) {
        if (tid < st) { red[tid].x += red[tid + st].x; red[tid].y += red[tid + st].y; }
        __syncthreads();
    }
    float m0 = red[0].x * (1.f / 256.f);
    float m1 = red[0].y * (1.f / 256.f);
    __syncthreads();

    float d0 = x.x - m0, d1 = x.y - m1;
    red[tid] = make_float2(d0 * d0, d1 * d1);
    __syncthreads();
    for (int st = 128; st > 0; st >>= 1) {
        if (tid < st) { red[tid].x += red[tid + st].x; red[tid].y += red[tid + st].y; }
        __syncthreads();
    }
    float v0 = red[0].x * (1.f / 256.f);
    float v1 = red[0].y * (1.f / 256.f);

    float w = knw[tid];
    float y0 = d0 * (1.0f / sqrtf(v0 + 1e-5f)) * w;
    float y1 = d1 * (1.0f / sqrtf(v1 + 1e-5f)) * w;

    float* Bk = s ? Bk2 : Bk1;
    size_t nbase = ((size_t)(h * KNUM + k) * 2) * KD;
    Bk[nbase + tid] = y0;
    Bk[nbase + KD + tid] = y1;
}

// ---------------- q layernorm (per 256-chunk of each 512 row) ---------------
__global__ __launch_bounds__(256) void qln_kernel(
    const float* __restrict__ qraw, const float* __restrict__ w,
    float* __restrict__ q1, float* __restrict__ q2)
{
    __shared__ float red[256];
    int b = blockIdx.x;
    int tid = threadIdx.x;
    for (int half = 0; half < 2; half++) {
        float x = qraw[(size_t)b * 512 + half * 256 + tid];
        red[tid] = x;
        __syncthreads();
        for (int st = 128; st > 0; st >>= 1) {
            if (tid < st) red[tid] += red[tid + st];
            __syncthreads();
        }
        float mean = red[0] * (1.f / 256.f);
        __syncthreads();
        float d = x - mean;
        red[tid] = d * d;
        __syncthreads();
        for (int st = 128; st > 0; st >>= 1) {
            if (tid < st) red[tid] += red[tid + st];
            __syncthreads();
        }
        float var = red[0] * (1.f / 256.f);
        __syncthreads();
        float y = d * (1.0f / sqrtf(var + 1e-5f)) * w[tid];
        (half ? q2 : q1)[(size_t)b * 256 + tid] = y;
    }
}

// ---------------- warp-resident top-32 of 1024 ------------------------------
// Executed by warp 0 (lanes 0..31). sc must hold 1024 valid floats.
// Writes 32 winning indices (set-correct; ties -> lower index) to out.
__device__ __forceinline__ void warp_top32(const float* sc, int* out)
{
    int lane = threadIdx.x & 31;
    float v[32];
#pragma unroll
    for (int j = 0; j < 32; j++) v[j] = sc[lane * 32 + j];

    float lm = NEG_INF; int lj = 0;
#pragma unroll
    for (int j = 0; j < 32; j++) if (v[j] > lm) { lm = v[j]; lj = j; }

    for (int r = 0; r < 32; r++) {
        float m = lm;
        int gi = lane * 32 + lj;
#pragma unroll
        for (int off = 16; off; off >>= 1) {
            float om = __shfl_xor_sync(0xffffffffu, m, off);
            int   og = __shfl_xor_sync(0xffffffffu, gi, off);
            if (om > m || (om == m && og < gi)) { m = om; gi = og; }
        }
        if (lane == 0) out[r] = gi;
        if ((gi >> 5) == lane) {
            int jz = gi & 31;
#pragma unroll
            for (int j = 0; j < 32; j++) if (j == jz) v[j] = NEG_INF;
            lm = NEG_INF; lj = 0;
#pragma unroll
            for (int j = 0; j < 32; j++) if (v[j] > lm) { lm = v[j]; lj = j; }
        }
    }
}

// ---------------- selection + tucker rerank + softmax + value gather --------
// One block per token b; handles both heads, accumulates agg row in smem.
__global__ __launch_bounds__(256) void select_kernel(
    const float* __restrict__ C1, const float* __restrict__ C2,
    const float* __restrict__ tu, const float* __restrict__ tv,
    const float* __restrict__ tc, const int* __restrict__ shuf,
    const float* __restrict__ values, float* __restrict__ agg)
{
    __shared__ float sc[1024];
    __shared__ float aggs[1024];
    __shared__ int sel1[32], sel2[32], selp[32];
    __shared__ float g1s[64], g2s[64];
    __shared__ float bw[32];
    __shared__ int bvi[32], bei[32];

    int tid = threadIdx.x;
    int b = blockIdx.x;

    for (int i = tid; i < 1024; i += 256) aggs[i] = 0.f;

    for (int h = 0; h < 2; ++h) {
        const float* c1 = C1 + (size_t)b * NCOL + h * 2048;
        const float* c2 = C2 + (size_t)b * NCOL + h * 2048;

        // s1 = s1r . tucker_u[h]
        float u0 = tu[h * 2 + 0], u1 = tu[h * 2 + 1];
        for (int k = tid; k < 1024; k += 256)
            sc[k] = c1[2 * k] * u0 + c1[2 * k + 1] * u1;
        __syncthreads();
        if (tid < 32) warp_top32(sc, sel1);
        __syncthreads();

        // s2 = s2r . tucker_v[h]
        float v0 = tv[h * 2 + 0], v1 = tv[h * 2 + 1];
        for (int k = tid; k < 1024; k += 256)
            sc[k] = c2[2 * k] * v0 + c2[2 * k + 1] * v1;
        __syncthreads();
        if (tid < 32) warp_top32(sc, sel2);
        __syncthreads();

        // gather rank pairs at selected indices
        if (tid < 32) {
            int k1 = sel1[tid];
            g1s[tid * 2 + 0] = c1[2 * k1];
            g1s[tid * 2 + 1] = c1[2 * k1 + 1];
            int k2 = sel2[tid];
            g2s[tid * 2 + 0] = c2[2 * k2];
            g2s[tid * 2 + 1] = c2[2 * k2 + 1];
        }
        __syncthreads();

        // core[h][r][s] summed over m: tc layout (m,h,r,s)
        float c00 = tc[4 * h + 0] + tc[8 + 4 * h + 0];
        float c01 = tc[4 * h + 1] + tc[8 + 4 * h + 1];
        float c10 = tc[4 * h + 2] + tc[8 + 4 * h + 2];
        float c11 = tc[4 * h + 3] + tc[8 + 4 * h + 3];

        // all 32x32 bilinear scores
        for (int p = tid; p < 1024; p += 256) {
            int k = p >> 5, l = p & 31;
            float a0 = g1s[2 * k], a1 = g1s[2 * k + 1];
            float t0 = a0 * c00 + a1 * c10;
            float t1 = a0 * c01 + a1 * c11;
            sc[p] = t0 * g2s[2 * l] + t1 * g2s[2 * l + 1];
        }
        __syncthreads();
        if (tid < 32) warp_top32(sc, selp);
        __syncthreads();

        // softmax + index decode (warp 0)
        if (tid < 32) {
            int p = selp[tid];
            float s = sc[p];
            float mx = s;
#pragma unroll
            for (int off = 16; off; off >>= 1)
                mx = fmaxf(mx, __shfl_xor_sync(0xffffffffu, mx, off));
            float e = expf(s - mx);
            float sum = e;
#pragma unroll
            for (int off = 16; off; off >>= 1)
                sum += __shfl_xor_sync(0xffffffffu, sum, off);
            bw[tid] = e / sum;
            int gi = sel1[p >> 5] * KNUM + sel2[p & 31];
            int sh = shuf[gi];
            bvi[tid] = sh & (VNUM - 1);
            bei[tid] = sh >> 18;
        }
        __syncthreads();

        // gather value rows (thread tid owns column tid), MLP-4 unrolled
#pragma unroll
        for (int j0 = 0; j0 < 32; j0 += 4) {
            float w0 = bw[j0 + 0], w1 = bw[j0 + 1], w2 = bw[j0 + 2], w3 = bw[j0 + 3];
            int e0 = bei[j0 + 0], e1 = bei[j0 + 1], e2 = bei[j0 + 2], e3 = bei[j0 + 3];
            float x0 = __ldg(&values[(size_t)bvi[j0 + 0] * VDIM + tid]);
            float x1 = __ldg(&values[(size_t)bvi[j0 + 1] * VDIM + tid]);
            float x2 = __ldg(&values[(size_t)bvi[j0 + 2] * VDIM + tid]);
            float x3 = __ldg(&values[(size_t)bvi[j0 + 3] * VDIM + tid]);
            aggs[e0 * 256 + tid] += w0 * x0;
            aggs[e1 * 256 + tid] += w1 * x1;
            aggs[e2 * 256 + tid] += w2 * x2;
            aggs[e3 * 256 + tid] += w3 * x3;
        }
        __syncthreads();
    }

    for (int i = tid; i < 1024; i += 256)
        agg[(size_t)b * 1024 + i] = aggs[i];
}

// ---------------- launch ----------------------------------------------------
extern "C" void kernel_launch(void* const* d_in, const int* in_sizes, int n_in,
                              void* d_out, int out_size)
{
    const float* hidden = (const float*)d_in[0];   // (2,2048,2048)
    const float* wq     = (const float*)d_in[1];   // (2048, 512)
    const float* qnw    = (const float*)d_in[2];   // (256)
    const float* knw    = (const float*)d_in[3];   // (256)
    const float* keys   = (const float*)d_in[4];   // (2,2,1024,256,2)
    const float* tcr    = (const float*)d_in[5];   // (2,2,2,2)
    const float* tu     = (const float*)d_in[6];   // (1,2,1,2)
    const float* tv     = (const float*)d_in[7];   // (1,2,1,2)
    const float* values = (const float*)d_in[8];   // (262144,256)
    const float* wv     = (const float*)d_in[9];   // (1024,2048)
    const int*   shuf   = (const int*)d_in[10];    // (1048576)
    float* out = (float*)d_out;

    float *qraw, *q1, *q2, *bk1, *bk2, *c1, *c2, *agg;
    cudaGetSymbolAddress((void**)&qraw, g_qraw);
    cudaGetSymbolAddress((void**)&q1,   g_q1);
    cudaGetSymbolAddress((void**)&q2,   g_q2);
    cudaGetSymbolAddress((void**)&bk1,  g_Bk1);
    cudaGetSymbolAddress((void**)&bk2,  g_Bk2);
    cudaGetSymbolAddress((void**)&c1,   g_C1);
    cudaGetSymbolAddress((void**)&c2,   g_C2);
    cudaGetSymbolAddress((void**)&agg,  g_agg);

    // 1) key normalization into transposed GEMM-ready layout
    keysn_kernel<<<4096, 256>>>(keys, knw, bk1, bk2);

    // 2) q = hidden @ wq  (4096 x 512 x 2048, NN)
    sgemm_kernel<false><<<dim3(512 / 128, BSZ / 128), 256>>>(hidden, wq, qraw, BSZ, 512, HID);

    // 3) layernorm q -> q1, q2
    qln_kernel<<<BSZ, 256>>>(qraw, qnw, q1, q2);

    // 4) score GEMMs (4096 x 4096 x 256, NT)
    sgemm_kernel<true><<<dim3(NCOL / 128, BSZ / 128), 256>>>(q1, bk1, c1, BSZ, NCOL, KD);
    sgemm_kernel<true><<<dim3(NCOL / 128, BSZ / 128), 256>>>(q2, bk2, c2, BSZ, NCOL, KD);

    // 5) top-k / tucker rerank / softmax / value aggregation
    select_kernel<<<BSZ, 256>>>(c1, c2, tu, tv, tcr, shuf, values, agg);

    // 6) out = agg @ wv  (4096 x 2048 x 1024, NN)
    sgemm_kernel<false><<<dim3(HID / 128, BSZ / 128), 256>>>(agg, wv, out, BSZ, HID, 1024);
}

// round 8
// speedup vs baseline: 1.2752x; 1.2752x over previous
#include <cuda_runtime.h>
#include <math.h>
#include <stdint.h>

// Problem constants (fixed shapes from setup_inputs)
#define BSZ   4096      // B*S
#define HID   2048      // H
#define KD    256       // KDIM
#define KNUM  1024      // key_num
#define NCOL  4096      // head * key_num * rank = 2*1024*2
#define VNUM  262144    // value_num = 2^18
#define VDIM  256
#define NEG_INF (-3.402823466e38f)

// ---------------- scratch (device globals; no allocation allowed) -----------
__device__ float g_qraw[(size_t)BSZ * 512];
__device__ float g_q1[(size_t)BSZ * KD];
__device__ float g_q2[(size_t)BSZ * KD];
__device__ float g_Bk1[(size_t)NCOL * KD];
__device__ float g_Bk2[(size_t)NCOL * KD];
__device__ float g_C1[(size_t)BSZ * NCOL];
__device__ float g_C2[(size_t)BSZ * NCOL];
__device__ float g_agg[(size_t)BSZ * 1024];

// ---------------- packed f32x2 FMA (Blackwell) ------------------------------
__device__ __forceinline__ unsigned long long ffma2(
    unsigned long long a, unsigned long long b, unsigned long long c)
{
    unsigned long long d;
    asm("fma.rn.f32x2 %0, %1, %2, %3;" : "=l"(d) : "l"(a), "l"(b), "l"(c));
    return d;
}
__device__ __forceinline__ unsigned long long bcast2(float x)
{
    unsigned long long p;
    asm("mov.b64 %0, {%1, %1};" : "=l"(p) : "r"(__float_as_uint(x)));
    return p;
}

// ---------------- fp32 SGEMM: C[M,N] = A[M,K] * B (proven R3 kernel) --------
// BT=false: B is (K,N) row-major (NN).  BT=true: B is (N,K) row-major (NT).
template <bool BT>
__device__ __forceinline__ void gload(
    const float* __restrict__ A, const float* __restrict__ B,
    int N, int K, int m0, int n0, int k0, int tid,
    float4 pa[2], float4 pb[2])
{
#pragma unroll
    for (int i = 0; i < 2; i++) {
        int idx4 = tid + i * 256;
        int row = idx4 >> 2, seg = idx4 & 3;
        pa[i] = *(const float4*)&A[(size_t)(m0 + row) * K + k0 + seg * 4];
    }
    if (!BT) {
#pragma unroll
        for (int i = 0; i < 2; i++) {
            int idx4 = tid + i * 256;
            int kk = idx4 >> 5, seg = idx4 & 31;
            pb[i] = *(const float4*)&B[(size_t)(k0 + kk) * N + n0 + seg * 4];
        }
    } else {
#pragma unroll
        for (int i = 0; i < 2; i++) {
            int idx4 = tid + i * 256;
            int nrow = idx4 >> 2, seg = idx4 & 3;
            pb[i] = *(const float4*)&B[(size_t)(n0 + nrow) * K + k0 + seg * 4];
        }
    }
}

template <bool BT>
__device__ __forceinline__ void sstore(
    float (*As)[132], float (*Bs)[132], int tid,
    const float4 pa[2], const float4 pb[2])
{
#pragma unroll
    for (int i = 0; i < 2; i++) {
        int idx4 = tid + i * 256;
        int row = idx4 >> 2, seg = idx4 & 3;
        As[seg * 4 + 0][row] = pa[i].x;
        As[seg * 4 + 1][row] = pa[i].y;
        As[seg * 4 + 2][row] = pa[i].z;
        As[seg * 4 + 3][row] = pa[i].w;
    }
    if (!BT) {
#pragma unroll
        for (int i = 0; i < 2; i++) {
            int idx4 = tid + i * 256;
            int kk = idx4 >> 5, seg = idx4 & 31;
            *(float4*)&Bs[kk][seg * 4] = pb[i];
        }
    } else {
#pragma unroll
        for (int i = 0; i < 2; i++) {
            int idx4 = tid + i * 256;
            int nrow = idx4 >> 2, seg = idx4 & 3;
            Bs[seg * 4 + 0][nrow] = pb[i].x;
            Bs[seg * 4 + 1][nrow] = pb[i].y;
            Bs[seg * 4 + 2][nrow] = pb[i].z;
            Bs[seg * 4 + 3][nrow] = pb[i].w;
        }
    }
}

template <bool BT>
__global__ __launch_bounds__(256, 2) void sgemm_kernel(
    const float* __restrict__ A, const float* __restrict__ B,
    float* __restrict__ C, int M, int N, int K)
{
    __shared__ float As[2][16][132];
    __shared__ float Bs[2][16][132];

    const int tid = threadIdx.x;
    const int tx = tid & 15;
    const int ty = tid >> 4;
    const int m0 = blockIdx.y * 128;
    const int n0 = blockIdx.x * 128;

    unsigned long long acc[8][4];
#pragma unroll
    for (int i = 0; i < 8; i++)
#pragma unroll
        for (int j = 0; j < 4; j++) acc[i][j] = 0ull;

    {
        float4 pa[2], pb[2];
        gload<BT>(A, B, N, K, m0, n0, 0, tid, pa, pb);
        sstore<BT>(As[0], Bs[0], tid, pa, pb);
    }
    __syncthreads();

    const int nk = K >> 4;
    int bf = 0;
    for (int t = 0; t < nk; t++) {
        float4 pa[2], pb[2];
        const bool more = (t + 1 < nk);
        if (more)
            gload<BT>(A, B, N, K, m0, n0, (t + 1) << 4, tid, pa, pb);

#pragma unroll
        for (int kk = 0; kk < 16; kk++) {
            float4 a0 = *(const float4*)&As[bf][kk][ty * 8 + 0];
            float4 a1 = *(const float4*)&As[bf][kk][ty * 8 + 4];
            ulonglong2 bq0 = *(const ulonglong2*)&Bs[bf][kk][tx * 8 + 0];
            ulonglong2 bq1 = *(const ulonglong2*)&Bs[bf][kk][tx * 8 + 4];
            unsigned long long bp[4] = {bq0.x, bq0.y, bq1.x, bq1.y};
            float ra[8] = {a0.x, a0.y, a0.z, a0.w, a1.x, a1.y, a1.z, a1.w};
#pragma unroll
            for (int i = 0; i < 8; i++) {
                unsigned long long ap = bcast2(ra[i]);
#pragma unroll
                for (int j = 0; j < 4; j++)
                    acc[i][j] = ffma2(ap, bp[j], acc[i][j]);
            }
        }

        if (more)
            sstore<BT>(As[bf ^ 1], Bs[bf ^ 1], tid, pa, pb);
        __syncthreads();
        bf ^= 1;
    }

#pragma unroll
    for (int i = 0; i < 8; i++) {
        float2 p0 = *reinterpret_cast<float2*>(&acc[i][0]);
        float2 p1 = *reinterpret_cast<float2*>(&acc[i][1]);
        float2 p2 = *reinterpret_cast<float2*>(&acc[i][2]);
        float2 p3 = *reinterpret_cast<float2*>(&acc[i][3]);
        size_t row = (size_t)(m0 + ty * 8 + i) * N + n0 + tx * 8;
        *(float4*)&C[row]     = make_float4(p0.x, p0.y, p1.x, p1.y);
        *(float4*)&C[row + 4] = make_float4(p2.x, p2.y, p3.x, p3.y);
    }
}

// ---------------- keys normalization -> transposed layout -------------------
__global__ __launch_bounds__(256) void keysn_kernel(
    const float* __restrict__ keys, const float* __restrict__ knw,
    float* __restrict__ Bk1, float* __restrict__ Bk2)
{
    __shared__ float2 red[256];
    int blk = blockIdx.x;
    int k = blk & (KNUM - 1);
    int s = (blk >> 10) & 1;
    int h = blk >> 11;
    int tid = threadIdx.x;

    const float* base = keys + ((((size_t)h * 2 + s) * KNUM + k) * KD) * 2;
    float2 x = *(const float2*)&base[tid * 2];

    red[tid] = x;
    __syncthreads();
    for (int st = 128; st > 0; st >>= 1) {
        if (tid < st) { red[tid].x += red[tid + st].x; red[tid].y += red[tid + st].y; }
        __syncthreads();
    }
    float m0 = red[0].x * (1.f / 256.f);
    float m1 = red[0].y * (1.f / 256.f);
    __syncthreads();

    float d0 = x.x - m0, d1 = x.y - m1;
    red[tid] = make_float2(d0 * d0, d1 * d1);
    __syncthreads();
    for (int st = 128; st > 0; st >>= 1) {
        if (tid < st) { red[tid].x += red[tid + st].x; red[tid].y += red[tid + st].y; }
        __syncthreads();
    }
    float v0 = red[0].x * (1.f / 256.f);
    float v1 = red[0].y * (1.f / 256.f);

    float w = knw[tid];
    float y0 = d0 * (1.0f / sqrtf(v0 + 1e-5f)) * w;
    float y1 = d1 * (1.0f / sqrtf(v1 + 1e-5f)) * w;

    float* Bk = s ? Bk2 : Bk1;
    size_t nbase = ((size_t)(h * KNUM + k) * 2) * KD;
    Bk[nbase + tid] = y0;
    Bk[nbase + KD + tid] = y1;
}

// ---------------- q layernorm (per 256-chunk of each 512 row) ---------------
__global__ __launch_bounds__(256) void qln_kernel(
    const float* __restrict__ qraw, const float* __restrict__ w,
    float* __restrict__ q1, float* __restrict__ q2)
{
    __shared__ float red[256];
    int b = blockIdx.x;
    int tid = threadIdx.x;
    for (int half = 0; half < 2; half++) {
        float x = qraw[(size_t)b * 512 + half * 256 + tid];
        red[tid] = x;
        __syncthreads();
        for (int st = 128; st > 0; st >>= 1) {
            if (tid < st) red[tid] += red[tid + st];
            __syncthreads();
        }
        float mean = red[0] * (1.f / 256.f);
        __syncthreads();
        float d = x - mean;
        red[tid] = d * d;
        __syncthreads();
        for (int st = 128; st > 0; st >>= 1) {
            if (tid < st) red[tid] += red[tid + st];
            __syncthreads();
        }
        float var = red[0] * (1.f / 256.f);
        __syncthreads();
        float y = d * (1.0f / sqrtf(var + 1e-5f)) * w[tid];
        (half ? q2 : q1)[(size_t)b * 256 + tid] = y;
    }
}

// ---------------- block-wide radix top-32 of 1024 ---------------------------
// Monotone key: float -> uint, order-preserving.
__device__ __forceinline__ uint32_t fkey(float f) {
    uint32_t u = __float_as_uint(f);
    return (u & 0x80000000u) ? ~u : (u | 0x80000000u);
}

// All 256 threads participate. sc[1024] valid. out[32] gets the top-32
// indices (set-exact; ties broken toward lower index, matching stable top_k).
// hist: 256 uints smem; scal: >=5 ints smem.
__device__ void block_top32(const float* sc, int* out, uint32_t* hist, int* scal)
{
    int tid = threadIdx.x;
    if (tid == 0) { scal[0] = 32; scal[1] = 0; scal[2] = 0; }
    __syncthreads();

    for (int lvl = 0; lvl < 4; lvl++) {
        int shift = 24 - 8 * lvl;
        hist[tid] = 0;
        __syncthreads();
        uint32_t pref = (uint32_t)scal[1];
#pragma unroll
        for (int i = 0; i < 4; i++) {
            uint32_t k = fkey(sc[tid + i * 256]);
            bool cand = (lvl == 0) || ((k >> (shift + 8)) == pref);
            if (cand) atomicAdd(&hist[(k >> shift) & 255u], 1u);
        }
        __syncthreads();
        if (tid < 32) {
            int lane = tid;
            int base = 255 - 8 * lane;          // descending groups of 8 bins
            uint32_t gs = 0;
#pragma unroll
            for (int j = 0; j < 8; j++) gs += hist[base - j];
            uint32_t s = gs;                     // inclusive scan, lane0 = top
#pragma unroll
            for (int o = 1; o < 32; o <<= 1) {
                uint32_t t = __shfl_up_sync(0xffffffffu, s, o);
                if (lane >= o) s += t;
            }
            int need = scal[0];
            uint32_t bal = __ballot_sync(0xffffffffu, (int)s >= need);
            int L = __ffs(bal) - 1;
            if (lane == L) {
                uint32_t acc = s - gs;           // strictly above this group
                for (int j = 0; j < 8; j++) {
                    uint32_t hcur = hist[base - j];
                    if (acc + hcur >= (uint32_t)need) {
                        scal[3] = base - j;      // chosen byte
                        scal[4] = (int)acc;      // strictly-above count
                        break;
                    }
                    acc += hcur;
                }
            }
        }
        __syncthreads();
        if (tid == 0) {
            scal[0] -= scal[4];
            scal[1] = (int)(((uint32_t)scal[1] << 8) | (uint32_t)scal[3]);
        }
        __syncthreads();
    }

    uint32_t T = (uint32_t)scal[1];
    int tieFill = scal[0];
    // strictly greater than threshold: exactly 32 - tieFill of them
#pragma unroll
    for (int i = 0; i < 4; i++) {
        int idx = tid + i * 256;
        if (fkey(sc[idx]) > T) {
            int p = atomicAdd(&scal[2], 1);
            out[p] = idx;
        }
    }
    __syncthreads();
    // ties at threshold, lowest index first (warp 0)
    if (tid < 32 && tieFill > 0) {
        int base_out = 32 - tieFill;
        int filled = 0;
        for (int base = 0; base < 1024 && filled < tieFill; base += 32) {
            uint32_t k = fkey(sc[base + tid]);
            uint32_t m = __ballot_sync(0xffffffffu, k == T);
            while (m && filled < tieFill) {
                int l = __ffs(m) - 1; m &= m - 1;
                if (tid == 0) out[base_out + filled] = base + l;
                filled++;
            }
        }
    }
    __syncthreads();
}

// ---------------- selection + tucker rerank + softmax + value gather --------
__global__ __launch_bounds__(256) void select_kernel(
    const float* __restrict__ C1, const float* __restrict__ C2,
    const float* __restrict__ tu, const float* __restrict__ tv,
    const float* __restrict__ tc, const int* __restrict__ shuf,
    const float* __restrict__ values, float* __restrict__ agg)
{
    __shared__ float sc1[1024];          // s1 scores, later pair scores
    __shared__ float sc2[1024];          // s2 scores
    __shared__ float aggs[1024];
    __shared__ uint32_t hist[256];
    __shared__ int scal[5];
    __shared__ int sel1[32], sel2[32], selp[32];
    __shared__ float g1s[64], g2s[64];
    __shared__ float bw[32];
    __shared__ int bvi[32], bei[32];

    int tid = threadIdx.x;
    int b = blockIdx.x;

    for (int i = tid; i < 1024; i += 256) aggs[i] = 0.f;

    for (int h = 0; h < 2; ++h) {
        const float* c1 = C1 + (size_t)b * NCOL + h * 2048;
        const float* c2 = C2 + (size_t)b * NCOL + h * 2048;

        float u0 = tu[h * 2 + 0], u1 = tu[h * 2 + 1];
        float v0 = tv[h * 2 + 0], v1 = tv[h * 2 + 1];
        for (int k = tid; k < 1024; k += 256) {
            float2 p1 = *(const float2*)&c1[2 * k];
            float2 p2 = *(const float2*)&c2[2 * k];
            sc1[k] = p1.x * u0 + p1.y * u1;
            sc2[k] = p2.x * v0 + p2.y * v1;
        }
        __syncthreads();

        block_top32(sc1, sel1, hist, scal);
        block_top32(sc2, sel2, hist, scal);

        // gather rank pairs at selected indices
        if (tid < 32) {
            int k1 = sel1[tid];
            g1s[tid * 2 + 0] = c1[2 * k1];
            g1s[tid * 2 + 1] = c1[2 * k1 + 1];
            int k2 = sel2[tid];
            g2s[tid * 2 + 0] = c2[2 * k2];
            g2s[tid * 2 + 1] = c2[2 * k2 + 1];
        }
        __syncthreads();

        // core[h][r][s] summed over m: tc layout (m,h,r,s)
        float c00 = tc[4 * h + 0] + tc[8 + 4 * h + 0];
        float c01 = tc[4 * h + 1] + tc[8 + 4 * h + 1];
        float c10 = tc[4 * h + 2] + tc[8 + 4 * h + 2];
        float c11 = tc[4 * h + 3] + tc[8 + 4 * h + 3];

        // all 32x32 bilinear scores -> sc1 (s1 scores no longer needed)
        for (int p = tid; p < 1024; p += 256) {
            int k = p >> 5, l = p & 31;
            float a0 = g1s[2 * k], a1 = g1s[2 * k + 1];
            float t0 = a0 * c00 + a1 * c10;
            float t1 = a0 * c01 + a1 * c11;
            sc1[p] = t0 * g2s[2 * l] + t1 * g2s[2 * l + 1];
        }
        __syncthreads();

        block_top32(sc1, selp, hist, scal);

        // softmax + index decode (warp 0)
        if (tid < 32) {
            int p = selp[tid];
            float s = sc1[p];
            float mx = s;
#pragma unroll
            for (int off = 16; off; off >>= 1)
                mx = fmaxf(mx, __shfl_xor_sync(0xffffffffu, mx, off));
            float e = expf(s - mx);
            float sum = e;
#pragma unroll
            for (int off = 16; off; off >>= 1)
                sum += __shfl_xor_sync(0xffffffffu, sum, off);
            bw[tid] = e / sum;
            int gi = sel1[p >> 5] * KNUM + sel2[p & 31];
            int sh = shuf[gi];
            bvi[tid] = sh & (VNUM - 1);
            bei[tid] = sh >> 18;
        }
        __syncthreads();

        // gather value rows (thread tid owns column tid), MLP-4 unrolled
#pragma unroll
        for (int j0 = 0; j0 < 32; j0 += 4) {
            float w0 = bw[j0 + 0], w1 = bw[j0 + 1], w2 = bw[j0 + 2], w3 = bw[j0 + 3];
            int e0 = bei[j0 + 0], e1 = bei[j0 + 1], e2 = bei[j0 + 2], e3 = bei[j0 + 3];
            float x0 = __ldg(&values[(size_t)bvi[j0 + 0] * VDIM + tid]);
            float x1 = __ldg(&values[(size_t)bvi[j0 + 1] * VDIM + tid]);
            float x2 = __ldg(&values[(size_t)bvi[j0 + 2] * VDIM + tid]);
            float x3 = __ldg(&values[(size_t)bvi[j0 + 3] * VDIM + tid]);
            aggs[e0 * 256 + tid] += w0 * x0;
            aggs[e1 * 256 + tid] += w1 * x1;
            aggs[e2 * 256 + tid] += w2 * x2;
            aggs[e3 * 256 + tid] += w3 * x3;
        }
        __syncthreads();
    }

    for (int i = tid; i < 1024; i += 256)
        agg[(size_t)b * 1024 + i] = aggs[i];
}

// ---------------- launch ----------------------------------------------------
extern "C" void kernel_launch(void* const* d_in, const int* in_sizes, int n_in,
                              void* d_out, int out_size)
{
    const float* hidden = (const float*)d_in[0];   // (2,2048,2048)
    const float* wq     = (const float*)d_in[1];   // (2048, 512)
    const float* qnw    = (const float*)d_in[2];   // (256)
    const float* knw    = (const float*)d_in[3];   // (256)
    const float* keys   = (const float*)d_in[4];   // (2,2,1024,256,2)
    const float* tcr    = (const float*)d_in[5];   // (2,2,2,2)
    const float* tu     = (const float*)d_in[6];   // (1,2,1,2)
    const float* tv     = (const float*)d_in[7];   // (1,2,1,2)
    const float* values = (const float*)d_in[8];   // (262144,256)
    const float* wv     = (const float*)d_in[9];   // (1024,2048)
    const int*   shuf   = (const int*)d_in[10];    // (1048576)
    float* out = (float*)d_out;

    float *qraw, *q1, *q2, *bk1, *bk2, *c1, *c2, *agg;
    cudaGetSymbolAddress((void**)&qraw, g_qraw);
    cudaGetSymbolAddress((void**)&q1,   g_q1);
    cudaGetSymbolAddress((void**)&q2,   g_q2);
    cudaGetSymbolAddress((void**)&bk1,  g_Bk1);
    cudaGetSymbolAddress((void**)&bk2,  g_Bk2);
    cudaGetSymbolAddress((void**)&c1,   g_C1);
    cudaGetSymbolAddress((void**)&c2,   g_C2);
    cudaGetSymbolAddress((void**)&agg,  g_agg);

    // 1) key normalization into transposed GEMM-ready layout
    keysn_kernel<<<4096, 256>>>(keys, knw, bk1, bk2);

    // 2) q = hidden @ wq  (4096 x 512 x 2048, NN)
    sgemm_kernel<false><<<dim3(512 / 128, BSZ / 128), 256>>>(hidden, wq, qraw, BSZ, 512, HID);

    // 3) layernorm q -> q1, q2
    qln_kernel<<<BSZ, 256>>>(qraw, qnw, q1, q2);

    // 4) score GEMMs (4096 x 4096 x 256, NT)
    sgemm_kernel<true><<<dim3(NCOL / 128, BSZ / 128), 256>>>(q1, bk1, c1, BSZ, NCOL, KD);
    sgemm_kernel<true><<<dim3(NCOL / 128, BSZ / 128), 256>>>(q2, bk2, c2, BSZ, NCOL, KD);

    // 5) top-k / tucker rerank / softmax / value aggregation
    select_kernel<<<BSZ, 256>>>(c1, c2, tu, tv, tcr, shuf, values, agg);

    // 6) out = agg @ wv  (4096 x 2048 x 1024, NN)
    sgemm_kernel<false><<<dim3(HID / 128, BSZ / 128), 256>>>(agg, wv, out, BSZ, HID, 1024);
}